// round 6
// baseline (speedup 1.0000x reference)
#include <cuda_runtime.h>
#include <math.h>

#define NN 20000
#define NE 2000
#define DD 64
#define NS 3
#define EPAD 2048

// pass_et: e-tile 256 x 8 blocks, 37 row-splits -> 296 blocks = 2/SM, one wave
#define ET_TK 25
#define ET_NSPLIT 37
// pass_n: n-tile 64, 128 threads, TK 40
#define PN_TK 40

typedef unsigned long long u64;

// ---------------- scratch (static device globals; no allocation) ----------------
__device__ float g_expA[NN * NE];   // exp(adj[s]) materialized once per subgraph
__device__ float g_x[NN * DD];      // fe @ W2
__device__ float g_y[EPAD * DD];    // relu(edge) @ W3
__device__ float g_node[NN * DD];   // pre-BN node
__device__ float g_acc[EPAD * DD];  // pass1 split-K accumulator
__device__ float g_acc2[EPAD * DD]; // pass3 split-K accumulator
__device__ float g_csum[EPAD];      // column exp-sums

// ---------------- f32x2 helpers ----------------
__device__ __forceinline__ u64 dup2(float x) {
    u64 r; asm("mov.b64 %0, {%1, %1};" : "=l"(r) : "f"(x)); return r;
}
__device__ __forceinline__ float2 unpk(u64 v) {
    float2 r; asm("mov.b64 {%0, %1}, %2;" : "=f"(r.x), "=f"(r.y) : "l"(v)); return r;
}
__device__ __forceinline__ void fma2(u64& d, u64 a, u64 b) {
    asm("fma.rn.f32x2 %0, %1, %2, %0;" : "+l"(d) : "l"(a), "l"(b));
}
__device__ __forceinline__ void red4(float* p, float a, float b, float c, float d) {
    asm volatile("red.global.add.v4.f32 [%0], {%1, %2, %3, %4};"
                 :: "l"(p), "f"(a), "f"(b), "f"(c), "f"(d) : "memory");
}

// ---------------- zero scratch (grid 512x256 == EPAD*DD exactly) ----------------
__global__ void zero_scratch_kernel() {
    int i = blockIdx.x * blockDim.x + threadIdx.x;
    g_acc[i]  = 0.f;
    g_acc2[i] = 0.f;
    if (i < EPAD) g_csum[i] = 0.f;
}

// ---------------- x = fe @ W2   [N,64]x[64,64] ----------------
__global__ __launch_bounds__(256) void gemm_x_kernel(const float* __restrict__ Fe,
                                                     const float* __restrict__ W2) {
    __shared__ __align__(16) float Fs[64][64];
    __shared__ __align__(16) float Ws[64][64];
    const int t  = threadIdx.x;
    const int n0 = blockIdx.x * 64;
    const int tx = t & 15, ty = t >> 4;
#pragma unroll
    for (int i = 0; i < 16; i++) {
        int idx = t + 256 * i;
        int r = idx >> 6, c = idx & 63;
        int n = n0 + r;
        Fs[r][c] = (n < NN) ? Fe[n * DD + c] : 0.f;
        Ws[r][c] = W2[idx];
    }
    __syncthreads();
    float a[4][4];
#pragma unroll
    for (int i = 0; i < 4; i++)
#pragma unroll
        for (int j = 0; j < 4; j++) a[i][j] = 0.f;
#pragma unroll
    for (int k = 0; k < 64; k++) {
        float fv[4];
#pragma unroll
        for (int i = 0; i < 4; i++) fv[i] = Fs[ty * 4 + i][k];
        float4 w4 = *(const float4*)&Ws[k][tx * 4];
        float wv[4] = {w4.x, w4.y, w4.z, w4.w};
#pragma unroll
        for (int i = 0; i < 4; i++)
#pragma unroll
            for (int j = 0; j < 4; j++) a[i][j] = fmaf(fv[i], wv[j], a[i][j]);
    }
#pragma unroll
    for (int i = 0; i < 4; i++) {
        int n = n0 + ty * 4 + i;
        if (n < NN) {
#pragma unroll
            for (int j = 0; j < 4; j++) g_x[n * DD + tx * 4 + j] = a[i][j];
        }
    }
}

// ---------------- pass 1 / pass 3: acc[e,d] += sum_n expA[n,e] * X[n,d] --------
// PASS==1: X=g_x, acc=g_acc; computes exp(A), writes g_expA, accumulates g_csum.
// PASS==3: X=g_node, acc=g_acc2; reads g_expA.
// Block: 256 threads, tile 256e x 64d, per-thread 8x8 via f32x2 (row-paired accs).
template <int PASS>
__global__ __launch_bounds__(256, 2) void pass_et_kernel(const float* __restrict__ A) {
    const float* __restrict__ X = (PASS == 1) ? g_x : g_node;
    float* __restrict__ acc = (PASS == 1) ? g_acc : g_acc2;
    __shared__ __align__(16) float Ps[ET_TK][256];
    __shared__ __align__(16) float Xs[ET_TK][64];
    const int t      = threadIdx.x;
    const int e_base = blockIdx.x * 256;
    const int split  = blockIdx.y;
    // 20000 = 20*541 + 17*540
    const int row0   = split * 540 + (split < 20 ? split : 20);
    const int nrows  = 540 + (split < 20 ? 1 : 0);
    const int tx8 = t & 7;      // d cols tx8*8 .. +7
    const int ty8 = t >> 3;     // e rows ty8*8 .. +7
    const int e_col  = e_base + t;
    const bool e_ok  = e_col < NE;

    u64 av[4][8];
#pragma unroll
    for (int r = 0; r < 4; r++)
#pragma unroll
        for (int c = 0; c < 8; c++) av[r][c] = 0ull;
    float cs = 0.f;

    for (int k0 = 0; k0 < nrows; k0 += ET_TK) {
        // load P tile: thread t owns e-column t, 25 rows
#pragma unroll
        for (int i = 0; i < ET_TK; i++) {
            float v = 0.f;
            int kk = k0 + i;
            if (kk < nrows && e_ok) {
                int row = row0 + kk;
                if (PASS == 1) {
                    v = __expf(A[row * NE + e_col]);
                    g_expA[row * NE + e_col] = v;
                    cs += v;
                } else {
                    v = g_expA[row * NE + e_col];
                }
            }
            Ps[i][t] = v;
        }
        // load X tile [25][64]
#pragma unroll
        for (int i = 0; i < 7; i++) {
            int idx = t + 256 * i;
            if (idx < ET_TK * 64) {
                int k = idx >> 6, d = idx & 63;
                float v = 0.f;
                if (k0 + k < nrows) v = X[(row0 + k0 + k) * DD + d];
                Xs[k][d] = v;
            }
        }
        __syncthreads();
#pragma unroll
        for (int k = 0; k < ET_TK; k++) {
            ulonglong2 pA = *(const ulonglong2*)&Ps[k][ty8 * 8];
            ulonglong2 pB = *(const ulonglong2*)&Ps[k][ty8 * 8 + 4];
            float4 xA = *(const float4*)&Xs[k][tx8 * 8];
            float4 xB = *(const float4*)&Xs[k][tx8 * 8 + 4];
            u64 xd[8];
            xd[0] = dup2(xA.x); xd[1] = dup2(xA.y); xd[2] = dup2(xA.z); xd[3] = dup2(xA.w);
            xd[4] = dup2(xB.x); xd[5] = dup2(xB.y); xd[6] = dup2(xB.z); xd[7] = dup2(xB.w);
            u64 pr[4] = {pA.x, pA.y, pB.x, pB.y};
#pragma unroll
            for (int r = 0; r < 4; r++)
#pragma unroll
                for (int c = 0; c < 8; c++) fma2(av[r][c], pr[r], xd[c]);
        }
        __syncthreads();
    }
    // epilogue: vectorized global reductions
#pragma unroll
    for (int r = 0; r < 4; r++) {
        float2 v[8];
#pragma unroll
        for (int c = 0; c < 8; c++) v[c] = unpk(av[r][c]);
        int e0r = e_base + ty8 * 8 + r * 2;
        if (e0r < NE) {
            red4(&acc[e0r * DD + tx8 * 8],     v[0].x, v[1].x, v[2].x, v[3].x);
            red4(&acc[e0r * DD + tx8 * 8 + 4], v[4].x, v[5].x, v[6].x, v[7].x);
        }
        if (e0r + 1 < NE) {
            red4(&acc[(e0r + 1) * DD + tx8 * 8],     v[0].y, v[1].y, v[2].y, v[3].y);
            red4(&acc[(e0r + 1) * DD + tx8 * 8 + 4], v[4].y, v[5].y, v[6].y, v[7].y);
        }
    }
    if (PASS == 1 && e_ok) atomicAdd(&g_csum[e_col], cs);
}

// ---------------- finalize1: edge = relu(acc/csum); y = edge @ W3 ----------------
__global__ __launch_bounds__(256) void finalize1_kernel(const float* __restrict__ W3) {
    __shared__ __align__(16) float Es[64][64];
    __shared__ __align__(16) float Ws[64][64];
    const int t  = threadIdx.x;
    const int e0 = blockIdx.x * 64;
    const int tx = t & 15, ty = t >> 4;
#pragma unroll
    for (int i = 0; i < 16; i++) {
        int idx = t + 256 * i;
        int r = idx >> 6, c = idx & 63;
        int ge = e0 + r;
        float v = 0.f;
        if (ge < NE) v = fmaxf(g_acc[ge * DD + c] / g_csum[ge], 0.f);
        Es[r][c] = v;
        Ws[r][c] = W3[idx];
    }
    __syncthreads();
    float a[4][4];
#pragma unroll
    for (int i = 0; i < 4; i++)
#pragma unroll
        for (int j = 0; j < 4; j++) a[i][j] = 0.f;
#pragma unroll
    for (int k = 0; k < 64; k++) {
        float ev[4];
#pragma unroll
        for (int i = 0; i < 4; i++) ev[i] = Es[ty * 4 + i][k];
        float4 w4 = *(const float4*)&Ws[k][tx * 4];
        float wv[4] = {w4.x, w4.y, w4.z, w4.w};
#pragma unroll
        for (int i = 0; i < 4; i++)
#pragma unroll
            for (int j = 0; j < 4; j++) a[i][j] = fmaf(ev[i], wv[j], a[i][j]);
    }
#pragma unroll
    for (int i = 0; i < 4; i++) {
        int ge = e0 + ty * 4 + i;
        if (ge < NE) {
#pragma unroll
            for (int j = 0; j < 4; j++) g_y[ge * DD + tx * 4 + j] = a[i][j];
        }
    }
}

// ---------------- pass 2: node = relu( (sum_e expA[n,e] y[e,:]) / rsum[n] ) ----
// Block: 128 threads, tile 64n x 64d, per-thread 4x8 via f32x2; rowsum folded
// into the FMA stream as fma2(rs, p, {1,1}); each thread normalizes locally.
__global__ __launch_bounds__(128, 4) void pass_n_kernel() {
    __shared__ __align__(16) float PsT[PN_TK][68];   // stride 68: 16B-aligned rows, conflict-light
    __shared__ __align__(16) float Ys[PN_TK][64];
    const int t   = threadIdx.x;
    const int n0  = blockIdx.x * 64;
    const int tx8 = t & 7;      // d cols tx8*8 .. +7
    const int tyr = t >> 3;     // n rows tyr*4 .. +3
    u64 av[2][8];
#pragma unroll
    for (int r = 0; r < 2; r++)
#pragma unroll
        for (int c = 0; c < 8; c++) av[r][c] = 0ull;
    u64 rs[2] = {0ull, 0ull};
    const u64 ONE2 = dup2(1.0f);

    for (int e0 = 0; e0 < NE; e0 += PN_TK) {
        // load 64x40 expA tile, transposed into PsT[k][n]
#pragma unroll
        for (int i = 0; i < 20; i++) {
            int idx = t + 128 * i;
            int nr = idx / PN_TK;
            int k  = idx - nr * PN_TK;
            int n  = n0 + nr;
            PsT[k][nr] = (n < NN) ? g_expA[n * NE + e0 + k] : 0.f;
        }
        // load Y tile [40][64]
#pragma unroll
        for (int i = 0; i < 20; i++) {
            int idx = t + 128 * i;
            int k = idx >> 6, d = idx & 63;
            Ys[k][d] = g_y[(e0 + k) * DD + d];
        }
        __syncthreads();
#pragma unroll
        for (int k = 0; k < PN_TK; k++) {
            ulonglong2 p2 = *(const ulonglong2*)&PsT[k][tyr * 4];
            float4 yA = *(const float4*)&Ys[k][tx8 * 8];
            float4 yB = *(const float4*)&Ys[k][tx8 * 8 + 4];
            u64 yd[8];
            yd[0] = dup2(yA.x); yd[1] = dup2(yA.y); yd[2] = dup2(yA.z); yd[3] = dup2(yA.w);
            yd[4] = dup2(yB.x); yd[5] = dup2(yB.y); yd[6] = dup2(yB.z); yd[7] = dup2(yB.w);
            u64 pr[2] = {p2.x, p2.y};
            fma2(rs[0], pr[0], ONE2);
            fma2(rs[1], pr[1], ONE2);
#pragma unroll
            for (int r = 0; r < 2; r++)
#pragma unroll
                for (int c = 0; c < 8; c++) fma2(av[r][c], pr[r], yd[c]);
        }
        __syncthreads();
    }
    float2 s01 = unpk(rs[0]), s23 = unpk(rs[1]);
    float ri[4] = {1.f / s01.x, 1.f / s01.y, 1.f / s23.x, 1.f / s23.y};
#pragma unroll
    for (int r = 0; r < 2; r++) {
        float2 v[8];
#pragma unroll
        for (int c = 0; c < 8; c++) v[c] = unpk(av[r][c]);
        int n_lo = n0 + tyr * 4 + r * 2;
        if (n_lo < NN) {
            float s = ri[r * 2];
            float4 o0 = {fmaxf(v[0].x, 0.f) * s, fmaxf(v[1].x, 0.f) * s,
                         fmaxf(v[2].x, 0.f) * s, fmaxf(v[3].x, 0.f) * s};
            float4 o1 = {fmaxf(v[4].x, 0.f) * s, fmaxf(v[5].x, 0.f) * s,
                         fmaxf(v[6].x, 0.f) * s, fmaxf(v[7].x, 0.f) * s};
            *(float4*)&g_node[n_lo * DD + tx8 * 8]     = o0;
            *(float4*)&g_node[n_lo * DD + tx8 * 8 + 4] = o1;
        }
        if (n_lo + 1 < NN) {
            float s = ri[r * 2 + 1];
            float4 o0 = {fmaxf(v[0].y, 0.f) * s, fmaxf(v[1].y, 0.f) * s,
                         fmaxf(v[2].y, 0.f) * s, fmaxf(v[3].y, 0.f) * s};
            float4 o1 = {fmaxf(v[4].y, 0.f) * s, fmaxf(v[5].y, 0.f) * s,
                         fmaxf(v[6].y, 0.f) * s, fmaxf(v[7].y, 0.f) * s};
            *(float4*)&g_node[(n_lo + 1) * DD + tx8 * 8]     = o0;
            *(float4*)&g_node[(n_lo + 1) * DD + tx8 * 8 + 4] = o1;
        }
    }
}

// ---------------- finalize3: out_edges = BN(relu(acc2/csum)) ----------------
__global__ void finalize3_kernel(const float* __restrict__ gamma,
                                 const float* __restrict__ beta,
                                 float* __restrict__ out_edges) {
    int idx = blockIdx.x * 256 + threadIdx.x;
    if (idx < NE * DD) {
        int e = idx >> 6, d = idx & 63;
        float v = fmaxf(g_acc2[idx] / g_csum[e], 0.f);
        float scale = gamma[d] * rsqrtf(1.f + 1e-5f);
        out_edges[idx] = v * scale + beta[d];
    }
}

// ---------------- fusion: fe' = s0*fe + s1*BN(node), attention over {fe, node} ---
__global__ __launch_bounds__(256) void fusion_kernel(const float* __restrict__ fe_old,
                                                     const float* __restrict__ gamma,
                                                     const float* __restrict__ beta,
                                                     const float* __restrict__ w1,
                                                     const float* __restrict__ b1,
                                                     const float* __restrict__ w2,
                                                     float* __restrict__ out_nodes) {
    __shared__ float w1s[64 * 64];
    __shared__ float b1s[64], w2s[64], gs[64], bs[64];
    const int t = threadIdx.x;
#pragma unroll
    for (int i = 0; i < 16; i++) w1s[t + 256 * i] = w1[t + 256 * i];
    if (t < 64) {
        b1s[t] = b1[t];
        w2s[t] = w2[t];
        gs[t]  = gamma[t] * rsqrtf(1.f + 1e-5f);
        bs[t]  = beta[t];
    }
    __syncthreads();
    const int warp = t >> 5, lane = t & 31;
    const int NPW = 4;
    const int nbase = blockIdx.x * (8 * NPW) + warp * NPW;
    for (int it = 0; it < NPW; it++) {
        int n = nbase + it;
        if (n >= NN) break;                      // warp-uniform
        int off = n * DD;
        float f0 = fe_old[off + lane], f1 = fe_old[off + lane + 32];
        float nb0 = fmaf(g_node[off + lane],      gs[lane],      bs[lane]);
        float nb1 = fmaf(g_node[off + lane + 32], gs[lane + 32], bs[lane + 32]);
        float ha0 = b1s[lane], ha1 = b1s[lane + 32];
        float hb0 = ha0, hb1 = ha1;
#pragma unroll
        for (int k = 0; k < 64; k++) {
            float fk = __shfl_sync(0xffffffffu, (k < 32) ? f0 : f1, k & 31);
            float nk = __shfl_sync(0xffffffffu, (k < 32) ? nb0 : nb1, k & 31);
            float wa = w1s[k * 64 + lane];
            float wb = w1s[k * 64 + lane + 32];
            ha0 = fmaf(fk, wa, ha0); ha1 = fmaf(fk, wb, ha1);
            hb0 = fmaf(nk, wa, hb0); hb1 = fmaf(nk, wb, hb1);
        }
        ha0 = tanhf(ha0); ha1 = tanhf(ha1);
        hb0 = tanhf(hb0); hb1 = tanhf(hb1);
        float pa = ha0 * w2s[lane] + ha1 * w2s[lane + 32];
        float pb = hb0 * w2s[lane] + hb1 * w2s[lane + 32];
#pragma unroll
        for (int o = 16; o > 0; o >>= 1) {
            pa += __shfl_down_sync(0xffffffffu, pa, o);
            pb += __shfl_down_sync(0xffffffffu, pb, o);
        }
        pa = __shfl_sync(0xffffffffu, pa, 0);
        pb = __shfl_sync(0xffffffffu, pb, 0);
        float s0 = 1.f / (1.f + expf(pb - pa));   // softmax over {fe, node} (b2 cancels)
        out_nodes[off + lane]      = s0 * f0 + (1.f - s0) * nb0;
        out_nodes[off + lane + 32] = s0 * f1 + (1.f - s0) * nb1;
    }
}

// ---------------- launch ----------------
extern "C" void kernel_launch(void* const* d_in, const int* in_sizes, int n_in,
                              void* d_out, int out_size) {
    const float* fe    = (const float*)d_in[0];   // [N, D]
    const float* adj   = (const float*)d_in[1];   // [S, N, E]
    const float* W2    = (const float*)d_in[2];   // [D, D]
    const float* W3    = (const float*)d_in[3];   // [D, D]
    const float* gamma = (const float*)d_in[4];   // [D]
    const float* beta  = (const float*)d_in[5];   // [D]
    const float* fw1   = (const float*)d_in[6];   // [D, D]
    const float* fb1   = (const float*)d_in[7];   // [D]
    const float* fw2   = (const float*)d_in[8];   // [D, 1]
    // d_in[9] = fus_b2 (cancels in softmax), d_in[10] = root_idx (unused)
    float* out = (float*)d_out;

    const float* fe_cur = fe;
    for (int s = 0; s < NS; s++) {
        const float* A   = adj + (size_t)s * NN * NE;
        float* out_nodes = out + (size_t)s * (NN + NE) * DD;
        float* out_edges = out_nodes + (size_t)NN * DD;

        zero_scratch_kernel<<<(EPAD * DD) / 256, 256>>>();
        gemm_x_kernel<<<(NN + 63) / 64, 256>>>(fe_cur, W2);

        dim3 g_et(8, ET_NSPLIT);
        pass_et_kernel<1><<<g_et, 256>>>(A);               // exp+csum+expA + edge_pre
        finalize1_kernel<<<32, 256>>>(W3);                 // y = relu(edge) @ W3
        pass_n_kernel<<<(NN + 63) / 64, 128>>>();          // node (pre-BN)
        pass_et_kernel<3><<<g_et, 256>>>(A);               // edge2_pre (reads expA)
        finalize3_kernel<<<(NE * DD + 255) / 256, 256>>>(gamma, beta, out_edges);
        fusion_kernel<<<(NN + 31) / 32, 256>>>(fe_cur, gamma, beta, fw1, fb1, fw2, out_nodes);

        fe_cur = out_nodes;   // chained fe through the output buffer
    }
}

// round 8
// speedup vs baseline: 1.4933x; 1.4933x over previous
#include <cuda_runtime.h>
#include <math.h>

#define NN 20000
#define NE 2000
#define NS 3
#define EPAD 2048
#define NPAIR 10016          // n-pairs (20032/2)

typedef unsigned int u32;

// ---------------- scratch (__device__ globals; no allocation) ----------------
__device__ u32 g_Ph[(size_t)NPAIR * EPAD];   // packed bf16-hi pairs of exp(adj): [npair][e]
__device__ u32 g_Pl[(size_t)NPAIR * EPAD];   // packed bf16-lo pairs
__device__ u32 g_xTh[NPAIR * 64], g_xTl[NPAIR * 64];  // (fe@W2)^T as [npair][d]
__device__ u32 g_yTh[1024 * 64],  g_yTl[1024 * 64];   // (edge@W3)^T as [epair][d]
__device__ u32 g_nTh[NPAIR * 64], g_nTl[NPAIR * 64];  // node^T as [npair][d]
__device__ __align__(16) float g_acc [NE * 64];
__device__ __align__(16) float g_acc2[NE * 64];
__device__ float g_csum[NE];
__device__ __align__(16) float g_node[NN * 64];

// ---------------- helpers ----------------
__device__ __forceinline__ u32 bf16hi(float v) {      // RNE bf16, bits in top half
    u32 u = __float_as_uint(v);
    return (u + 0x7FFFu + ((u >> 16) & 1u)) & 0xFFFF0000u;
}
// pack (v0 -> low 16, v1 -> high 16) hi and lo parts
__device__ __forceinline__ void pack2(float v0, float v1, u32& h, u32& l) {
    u32 h0 = bf16hi(v0), h1 = bf16hi(v1);
    h = (h0 >> 16) | h1;
    u32 l0 = bf16hi(v0 - __uint_as_float(h0));
    u32 l1 = bf16hi(v1 - __uint_as_float(h1));
    l = (l0 >> 16) | l1;
}
__device__ __forceinline__ void MMA(float* c, const u32* a, const u32* b) {
    asm volatile("mma.sync.aligned.m16n8k16.row.col.f32.bf16.bf16.f32 "
        "{%0,%1,%2,%3}, {%4,%5,%6,%7}, {%8,%9}, {%0,%1,%2,%3};"
        : "+f"(c[0]), "+f"(c[1]), "+f"(c[2]), "+f"(c[3])
        : "r"(a[0]), "r"(a[1]), "r"(a[2]), "r"(a[3]), "r"(b[0]), "r"(b[1]));
}
__device__ __forceinline__ void red2(float* p, float a, float b) {
    asm volatile("red.global.add.v2.f32 [%0], {%1,%2};" :: "l"(p), "f"(a), "f"(b) : "memory");
}

// ---------------- zero scratch: 500x256 = NE*64 ----------------
__global__ void zero_scratch_kernel() {
    int i = blockIdx.x * 256 + threadIdx.x;
    g_acc[i]  = 0.f;
    g_acc2[i] = 0.f;
    if (i < NE) g_csum[i] = 0.f;
}

// ---------------- gemm_x: x = fe @ W2, writes xT [npair][d] hi/lo ----------------
__global__ __launch_bounds__(256) void gemm_x_kernel(const float* __restrict__ Fe,
                                                     const float* __restrict__ W2) {
    __shared__ __align__(16) float Fs[64][64];
    __shared__ __align__(16) float Ws[64][64];
    const int t  = threadIdx.x;
    const int n0 = blockIdx.x * 64;
    const int tx = t & 15, ty = t >> 4;
#pragma unroll
    for (int i = 0; i < 16; i++) {
        int idx = t + 256 * i;
        int r = idx >> 6, c = idx & 63;
        int n = n0 + r;
        Fs[r][c] = (n < NN) ? Fe[n * 64 + c] : 0.f;
        Ws[r][c] = W2[idx];
    }
    __syncthreads();
    float a[4][4];
#pragma unroll
    for (int i = 0; i < 4; i++)
#pragma unroll
        for (int j = 0; j < 4; j++) a[i][j] = 0.f;
#pragma unroll
    for (int k = 0; k < 64; k++) {
        float fv[4];
#pragma unroll
        for (int i = 0; i < 4; i++) fv[i] = Fs[ty * 4 + i][k];
        float4 w4 = *(const float4*)&Ws[k][tx * 4];
        float wv[4] = {w4.x, w4.y, w4.z, w4.w};
#pragma unroll
        for (int i = 0; i < 4; i++)
#pragma unroll
            for (int j = 0; j < 4; j++) a[i][j] = fmaf(fv[i], wv[j], a[i][j]);
    }
#pragma unroll
    for (int ip = 0; ip < 2; ip++)
#pragma unroll
        for (int j = 0; j < 4; j++) {
            u32 h, l; pack2(a[2 * ip][j], a[2 * ip + 1][j], h, l);
            int idx = ((n0 >> 1) + ty * 2 + ip) * 64 + tx * 4 + j;
            g_xTh[idx] = h;
            g_xTl[idx] = l;
        }
}

// ---------------- GEMM1/3: acc[e,d] += sum_n exp(adj[n,e]) * B[n,d] ----------------
// MODE 1: exp from adj, caches g_P, B=xT, ones->csum.  MODE 3: loads g_P, B=nT.
template <int MODE>
__global__ __launch_bounds__(256, 2) void gemm_et(const float* __restrict__ A) {
    extern __shared__ __align__(16) char sm[];
    u32* Ah = (u32*)sm;                  // [32 kpair][136]  (m = e, stride%32==8)
    u32* Al = Ah + 32 * 136;
    u32* Bh = Al + 32 * 136;             // [32 kpair][72]   (n = d + ones col 64)
    u32* Bl = Bh + 32 * 72;
    const int t = threadIdx.x, w = t >> 5, lane = t & 31;
    const int g = lane >> 2, tg = lane & 3;
    const int e0 = blockIdx.x * 128;
    const int sp = blockIdx.y;
    const int c0  = sp * 17 + (sp < 7 ? sp : 7);
    const int nch = 17 + (sp < 7 ? 1 : 0);
    const int wm = w >> 1, wn = w & 1;
    const int rowb = wm * 32;
    const int e_l = t & 127, half = t >> 7;
    const u32* __restrict__ BTh = (MODE == 1) ? g_xTh : g_nTh;
    const u32* __restrict__ BTl = (MODE == 1) ? g_xTl : g_nTl;

    float c[2][4][4];
    float ce[2][4];
#pragma unroll
    for (int mt = 0; mt < 2; mt++) {
#pragma unroll
        for (int nt = 0; nt < 4; nt++)
#pragma unroll
            for (int q = 0; q < 4; q++) c[mt][nt][q] = 0.f;
#pragma unroll
        for (int q = 0; q < 4; q++) ce[mt][q] = 0.f;
    }

    for (int ci = 0; ci < nch; ci++) {
        const int n0  = (c0 + ci) * 64;
        const int np0 = n0 >> 1;
        // ---- fill A tile [32 kpair][128 e] ----
        if (MODE == 1) {
            const bool e_ok = (e0 + e_l) < NE;
#pragma unroll
            for (int i = 0; i < 16; i++) {
                int p_l = 2 * i + half;
                int n = n0 + 2 * p_l;
                float v0 = 0.f, v1 = 0.f;
                if (e_ok) {
                    if (n < NN)     v0 = __expf(A[(size_t)n * NE + e0 + e_l]);
                    if (n + 1 < NN) v1 = __expf(A[(size_t)(n + 1) * NE + e0 + e_l]);
                }
                u32 h, l; pack2(v0, v1, h, l);
                Ah[p_l * 136 + e_l] = h;
                Al[p_l * 136 + e_l] = l;
                size_t gi = (size_t)(np0 + p_l) * EPAD + e0 + e_l;
                g_Ph[gi] = h;
                g_Pl[gi] = l;
            }
        } else {
#pragma unroll
            for (int i = 0; i < 16; i++) {
                int p_l = 2 * i + half;
                size_t gi = (size_t)(np0 + p_l) * EPAD + e0 + e_l;
                Ah[p_l * 136 + e_l] = g_Ph[gi];
                Al[p_l * 136 + e_l] = g_Pl[gi];
            }
        }
        // ---- fill B tile [32 kpair][64 d] + ones col ----
        {
            int d = t & 63;
#pragma unroll
            for (int i = 0; i < 8; i++) {
                int r = (t >> 6) + 4 * i;
                Bh[r * 72 + d] = BTh[(np0 + r) * 64 + d];
                Bl[r * 72 + d] = BTl[(np0 + r) * 64 + d];
            }
            int r = t >> 3, cc = 64 + (t & 7);
            Bh[r * 72 + cc] = (MODE == 1 && cc == 64) ? 0x3F803F80u : 0u;
            Bl[r * 72 + cc] = 0u;
        }
        __syncthreads();
        // ---- mma ----
#pragma unroll
        for (int kt = 0; kt < 4; kt++) {
            int kp = kt * 8;
            u32 ah[2][4], al[2][4];
#pragma unroll
            for (int mt = 0; mt < 2; mt++) {
                int rb = rowb + mt * 16;
                ah[mt][0] = Ah[(kp + tg) * 136 + rb + g];
                ah[mt][1] = Ah[(kp + tg) * 136 + rb + g + 8];
                ah[mt][2] = Ah[(kp + tg + 4) * 136 + rb + g];
                ah[mt][3] = Ah[(kp + tg + 4) * 136 + rb + g + 8];
                al[mt][0] = Al[(kp + tg) * 136 + rb + g];
                al[mt][1] = Al[(kp + tg) * 136 + rb + g + 8];
                al[mt][2] = Al[(kp + tg + 4) * 136 + rb + g];
                al[mt][3] = Al[(kp + tg + 4) * 136 + rb + g + 8];
            }
#pragma unroll
            for (int nt = 0; nt < 4; nt++) {
                int cb = wn * 32 + nt * 8;
                u32 bh[2] = { Bh[(kp + tg) * 72 + cb + g], Bh[(kp + tg + 4) * 72 + cb + g] };
                u32 bl[2] = { Bl[(kp + tg) * 72 + cb + g], Bl[(kp + tg + 4) * 72 + cb + g] };
#pragma unroll
                for (int mt = 0; mt < 2; mt++) {
                    MMA(c[mt][nt], ah[mt], bh);
                    MMA(c[mt][nt], ah[mt], bl);
                    MMA(c[mt][nt], al[mt], bh);
                }
            }
            if (MODE == 1 && wn == 1) {
                u32 be[2] = { Bh[(kp + tg) * 72 + 64 + g], Bh[(kp + tg + 4) * 72 + 64 + g] };
#pragma unroll
                for (int mt = 0; mt < 2; mt++) {
                    MMA(ce[mt], ah[mt], be);
                    MMA(ce[mt], al[mt], be);
                }
            }
        }
        __syncthreads();
    }
    // ---- epilogue: split-K reduce ----
    float* acc = (MODE == 1) ? g_acc : g_acc2;
#pragma unroll
    for (int mt = 0; mt < 2; mt++)
#pragma unroll
        for (int nt = 0; nt < 4; nt++) {
            int row = e0 + rowb + mt * 16 + g;
            int col = wn * 32 + nt * 8 + 2 * tg;
            if (row < NE)     red2(&acc[row * 64 + col],       c[mt][nt][0], c[mt][nt][1]);
            if (row + 8 < NE) red2(&acc[(row + 8) * 64 + col], c[mt][nt][2], c[mt][nt][3]);
        }
    if (MODE == 1 && wn == 1 && tg == 0) {
#pragma unroll
        for (int mt = 0; mt < 2; mt++) {
            int row = e0 + rowb + mt * 16 + g;
            if (row < NE)     atomicAdd(&g_csum[row],     ce[mt][0]);
            if (row + 8 < NE) atomicAdd(&g_csum[row + 8], ce[mt][2]);
        }
    }
}

// ---------------- finalize1: edge = relu(acc/csum); y = edge@W3 -> yT [epair][d] --
__global__ __launch_bounds__(256) void finalize1_kernel(const float* __restrict__ W3) {
    __shared__ __align__(16) float Es[64][64];
    __shared__ __align__(16) float Ws[64][64];
    const int t  = threadIdx.x;
    const int e0 = blockIdx.x * 64;
    const int tx = t & 15, ty = t >> 4;
#pragma unroll
    for (int i = 0; i < 16; i++) {
        int idx = t + 256 * i;
        int r = idx >> 6, cc = idx & 63;
        int ge = e0 + r;
        float v = 0.f;
        if (ge < NE) v = fmaxf(g_acc[ge * 64 + cc] / g_csum[ge], 0.f);
        Es[r][cc] = v;
        Ws[r][cc] = W3[idx];
    }
    __syncthreads();
    float a[4][4];
#pragma unroll
    for (int i = 0; i < 4; i++)
#pragma unroll
        for (int j = 0; j < 4; j++) a[i][j] = 0.f;
#pragma unroll
    for (int k = 0; k < 64; k++) {
        float ev[4];
#pragma unroll
        for (int i = 0; i < 4; i++) ev[i] = Es[ty * 4 + i][k];
        float4 w4 = *(const float4*)&Ws[k][tx * 4];
        float wv[4] = {w4.x, w4.y, w4.z, w4.w};
#pragma unroll
        for (int i = 0; i < 4; i++)
#pragma unroll
            for (int j = 0; j < 4; j++) a[i][j] = fmaf(ev[i], wv[j], a[i][j]);
    }
#pragma unroll
    for (int ip = 0; ip < 2; ip++)
#pragma unroll
        for (int j = 0; j < 4; j++) {
            u32 h, l; pack2(a[2 * ip][j], a[2 * ip + 1][j], h, l);
            int idx = ((e0 >> 1) + ty * 2 + ip) * 64 + tx * 4 + j;
            g_yTh[idx] = h;
            g_yTl[idx] = l;
        }
}

// ---------------- GEMM2: node = relu((exp(adj)@y)/rsum); writes g_node + nT ------
__global__ __launch_bounds__(256, 3) void gemm_n() {
    extern __shared__ __align__(16) char sm[];
    u32* A2h = (u32*)sm;                 // [64 n][36 epair]  (stride%32==4)
    u32* A2l = A2h + 64 * 36;
    u32* Bh  = A2l + 64 * 36;            // [32 epair][72]
    u32* Bl  = Bh + 32 * 72;
    float* rsum   = (float*)(Bl + 32 * 72);  // [64]
    float* bounce = (float*)sm;          // [64][68] overlay on A2 after mma done
    const int t = threadIdx.x, w = t >> 5, lane = t & 31;
    const int g = lane >> 2, tg = lane & 3;
    const int p0 = blockIdx.x * 32;      // n window = 64
    const int wm = w >> 1, wn = w & 1;
    const int rowb = wm * 16;

    float c[4][4];
    float ce[4];
#pragma unroll
    for (int nt = 0; nt < 4; nt++)
#pragma unroll
        for (int q = 0; q < 4; q++) c[nt][q] = 0.f;
#pragma unroll
    for (int q = 0; q < 4; q++) ce[q] = 0.f;

    for (int ech = 0; ech < 32; ech++) {
        const int e0 = ech * 64, ep0 = ech * 32;
        // ---- fill A2 [64 n][32 epair] via prmt repack of g_P ----
#pragma unroll
        for (int i = 0; i < 4; i++) {
            int pl = w + 8 * i;
            size_t base = (size_t)(p0 + pl) * EPAD + e0 + 2 * lane;
            uint2 vh = *(const uint2*)&g_Ph[base];
            uint2 vl = *(const uint2*)&g_Pl[base];
            A2h[(2 * pl) * 36 + lane]     = __byte_perm(vh.x, vh.y, 0x5410);
            A2h[(2 * pl + 1) * 36 + lane] = __byte_perm(vh.x, vh.y, 0x7632);
            A2l[(2 * pl) * 36 + lane]     = __byte_perm(vl.x, vl.y, 0x5410);
            A2l[(2 * pl + 1) * 36 + lane] = __byte_perm(vl.x, vl.y, 0x7632);
        }
        // ---- fill B [32 epair][64 d] + ones col ----
        {
            int d = t & 63;
#pragma unroll
            for (int i = 0; i < 8; i++) {
                int r = (t >> 6) + 4 * i;
                Bh[r * 72 + d] = g_yTh[(ep0 + r) * 64 + d];
                Bl[r * 72 + d] = g_yTl[(ep0 + r) * 64 + d];
            }
            int r = t >> 3, cc = 64 + (t & 7);
            Bh[r * 72 + cc] = (cc == 64) ? 0x3F803F80u : 0u;
            Bl[r * 72 + cc] = 0u;
        }
        __syncthreads();
#pragma unroll
        for (int kt = 0; kt < 4; kt++) {
            int kp = kt * 8;
            u32 ah[4] = { A2h[(rowb + g) * 36 + kp + tg],     A2h[(rowb + g + 8) * 36 + kp + tg],
                          A2h[(rowb + g) * 36 + kp + tg + 4], A2h[(rowb + g + 8) * 36 + kp + tg + 4] };
            u32 al[4] = { A2l[(rowb + g) * 36 + kp + tg],     A2l[(rowb + g + 8) * 36 + kp + tg],
                          A2l[(rowb + g) * 36 + kp + tg + 4], A2l[(rowb + g + 8) * 36 + kp + tg + 4] };
#pragma unroll
            for (int nt = 0; nt < 4; nt++) {
                int cb = wn * 32 + nt * 8;
                u32 bh[2] = { Bh[(kp + tg) * 72 + cb + g], Bh[(kp + tg + 4) * 72 + cb + g] };
                u32 bl[2] = { Bl[(kp + tg) * 72 + cb + g], Bl[(kp + tg + 4) * 72 + cb + g] };
                MMA(c[nt], ah, bh);
                MMA(c[nt], ah, bl);
                MMA(c[nt], al, bh);
            }
            if (wn == 1) {
                u32 be[2] = { Bh[(kp + tg) * 72 + 64 + g], Bh[(kp + tg + 4) * 72 + 64 + g] };
                MMA(ce, ah, be);
                MMA(ce, al, be);
            }
        }
        __syncthreads();
    }
    // ---- rsum from ones column ----
    if (wn == 1 && tg == 0) {
        rsum[rowb + g]     = ce[0];
        rsum[rowb + g + 8] = ce[2];
    }
    __syncthreads();
    float s0 = rsum[rowb + g],     ri0 = (s0 > 0.f) ? 1.f / s0 : 0.f;
    float s1 = rsum[rowb + g + 8], ri1 = (s1 > 0.f) ? 1.f / s1 : 0.f;
    __syncthreads();   // rsum read before bounce overlay... (rsum region separate; sync for A2 reuse)
#pragma unroll
    for (int nt = 0; nt < 4; nt++) {
        int col = wn * 32 + nt * 8 + 2 * tg;
        bounce[(rowb + g) * 68 + col]         = fmaxf(c[nt][0], 0.f) * ri0;
        bounce[(rowb + g) * 68 + col + 1]     = fmaxf(c[nt][1], 0.f) * ri0;
        bounce[(rowb + g + 8) * 68 + col]     = fmaxf(c[nt][2], 0.f) * ri1;
        bounce[(rowb + g + 8) * 68 + col + 1] = fmaxf(c[nt][3], 0.f) * ri1;
    }
    __syncthreads();
    const int n0 = p0 * 2;
#pragma unroll
    for (int i = 0; i < 4; i++) {            // g_node fp32 coalesced
        int idx = t + 256 * i;
        int r = idx >> 4, q = idx & 15;
        if (n0 + r < NN)
            *(float4*)&g_node[(n0 + r) * 64 + q * 4] = *(const float4*)&bounce[r * 68 + q * 4];
    }
#pragma unroll
    for (int i = 0; i < 8; i++) {            // nT [npair][d] hi/lo
        int idx = t + 256 * i;
        int d = idx & 63, pp = idx >> 6;
        u32 h, l;
        pack2(bounce[(2 * pp) * 68 + d], bounce[(2 * pp + 1) * 68 + d], h, l);
        g_nTh[(p0 + pp) * 64 + d] = h;
        g_nTl[(p0 + pp) * 64 + d] = l;
    }
}

// ---------------- finalize3: out_edges = BN(relu(acc2/csum)) ----------------
__global__ void finalize3_kernel(const float* __restrict__ gamma,
                                 const float* __restrict__ beta,
                                 float* __restrict__ out_edges) {
    int idx = blockIdx.x * 256 + threadIdx.x;
    if (idx < NE * 64) {
        int e = idx >> 6, d = idx & 63;
        float v = fmaxf(g_acc2[idx] / g_csum[e], 0.f);
        out_edges[idx] = v * (gamma[d] * rsqrtf(1.f + 1e-5f)) + beta[d];
    }
}

// ---------------- fusion: fe' = s0*fe + (1-s0)*BN(node) ----------------
__global__ __launch_bounds__(256) void fusion_kernel(const float* __restrict__ fe_old,
                                                     const float* __restrict__ gamma,
                                                     const float* __restrict__ beta,
                                                     const float* __restrict__ w1,
                                                     const float* __restrict__ b1,
                                                     const float* __restrict__ w2,
                                                     float* __restrict__ out_nodes) {
    __shared__ float w1s[64 * 64];
    __shared__ float b1s[64], w2s[64], gs[64], bs[64];
    const int t = threadIdx.x;
#pragma unroll
    for (int i = 0; i < 16; i++) w1s[t + 256 * i] = w1[t + 256 * i];
    if (t < 64) {
        b1s[t] = b1[t]; w2s[t] = w2[t];
        gs[t] = gamma[t] * rsqrtf(1.f + 1e-5f); bs[t] = beta[t];
    }
    __syncthreads();
    const int warp = t >> 5, lane = t & 31;
    const int nbase = blockIdx.x * 32 + warp * 4;
    for (int it = 0; it < 4; it++) {
        int n = nbase + it;
        if (n >= NN) break;
        int off = n * 64;
        float f0 = fe_old[off + lane], f1 = fe_old[off + lane + 32];
        float nb0 = fmaf(g_node[off + lane],      gs[lane],      bs[lane]);
        float nb1 = fmaf(g_node[off + lane + 32], gs[lane + 32], bs[lane + 32]);
        float ha0 = b1s[lane], ha1 = b1s[lane + 32];
        float hb0 = ha0, hb1 = ha1;
#pragma unroll
        for (int k = 0; k < 64; k++) {
            float fk = __shfl_sync(0xffffffffu, (k < 32) ? f0 : f1, k & 31);
            float nk = __shfl_sync(0xffffffffu, (k < 32) ? nb0 : nb1, k & 31);
            float wa = w1s[k * 64 + lane], wb = w1s[k * 64 + lane + 32];
            ha0 = fmaf(fk, wa, ha0); ha1 = fmaf(fk, wb, ha1);
            hb0 = fmaf(nk, wa, hb0); hb1 = fmaf(nk, wb, hb1);
        }
        ha0 = tanhf(ha0); ha1 = tanhf(ha1);
        hb0 = tanhf(hb0); hb1 = tanhf(hb1);
        float pa = ha0 * w2s[lane] + ha1 * w2s[lane + 32];
        float pb = hb0 * w2s[lane] + hb1 * w2s[lane + 32];
#pragma unroll
        for (int o = 16; o > 0; o >>= 1) {
            pa += __shfl_down_sync(0xffffffffu, pa, o);
            pb += __shfl_down_sync(0xffffffffu, pb, o);
        }
        pa = __shfl_sync(0xffffffffu, pa, 0);
        pb = __shfl_sync(0xffffffffu, pb, 0);
        float s0 = 1.f / (1.f + expf(pb - pa));
        out_nodes[off + lane]      = s0 * f0 + (1.f - s0) * nb0;
        out_nodes[off + lane + 32] = s0 * f1 + (1.f - s0) * nb1;
    }
}

// ---------------- launch ----------------
#define SM_ET ((32*136*2 + 32*72*2) * 4)            // 53248
#define SM_N  ((64*36*2 + 32*72*2) * 4 + 256)       // 37120

extern "C" void kernel_launch(void* const* d_in, const int* in_sizes, int n_in,
                              void* d_out, int out_size) {
    const float* fe    = (const float*)d_in[0];
    const float* adj   = (const float*)d_in[1];
    const float* W2    = (const float*)d_in[2];
    const float* W3    = (const float*)d_in[3];
    const float* gamma = (const float*)d_in[4];
    const float* beta  = (const float*)d_in[5];
    const float* fw1   = (const float*)d_in[6];
    const float* fb1   = (const float*)d_in[7];
    const float* fw2   = (const float*)d_in[8];
    float* out = (float*)d_out;

    cudaFuncSetAttribute((const void*)gemm_et<1>, cudaFuncAttributeMaxDynamicSharedMemorySize, SM_ET);
    cudaFuncSetAttribute((const void*)gemm_et<3>, cudaFuncAttributeMaxDynamicSharedMemorySize, SM_ET);
    cudaFuncSetAttribute((const void*)gemm_n,     cudaFuncAttributeMaxDynamicSharedMemorySize, SM_N);

    const float* fe_cur = fe;
    for (int s = 0; s < NS; s++) {
        const float* A   = adj + (size_t)s * NN * NE;
        float* out_nodes = out + (size_t)s * (NN + NE) * 64;
        float* out_edges = out_nodes + (size_t)NN * 64;

        zero_scratch_kernel<<<500, 256>>>();
        gemm_x_kernel<<<313, 256>>>(fe_cur, W2);
        gemm_et<1><<<dim3(16, 18), 256, SM_ET>>>(A);   // exp + cache g_P + edge_pre + csum
        finalize1_kernel<<<32, 256>>>(W3);             // y = relu(edge)@W3 -> yT
        gemm_n<<<313, 256, SM_N>>>();                  // node + nT (+rsum via ones col)
        gemm_et<3><<<dim3(16, 18), 256, SM_ET>>>(A);   // edge2_pre from cached g_P
        finalize3_kernel<<<500, 256>>>(gamma, beta, out_edges);
        fusion_kernel<<<625, 256>>>(fe_cur, gamma, beta, fw1, fb1, fw2, out_nodes);

        fe_cur = out_nodes;
    }
}

// round 9
// speedup vs baseline: 1.5163x; 1.0155x over previous
#include <cuda_runtime.h>
#include <math.h>

#define NN 20000
#define NE 2000
#define NS 3
#define EPAD 2048
#define NPAIR 10016          // n-pairs (20032/2)

typedef unsigned int u32;

// ---------------- scratch (__device__ globals; no allocation) ----------------
__device__ u32 g_Ph[(size_t)NPAIR * EPAD];   // packed bf16-hi pairs of exp(adj): [npair][e]
__device__ u32 g_Pl[(size_t)NPAIR * EPAD];   // packed bf16-lo pairs
__device__ u32 g_xTh[NPAIR * 64], g_xTl[NPAIR * 64];  // (fe@W2)^T as [npair][d]
__device__ u32 g_yTh[1024 * 64],  g_yTl[1024 * 64];   // (edge@W3)^T as [epair][d]
__device__ u32 g_nTh[NPAIR * 64], g_nTl[NPAIR * 64];  // node^T as [npair][d]
__device__ __align__(16) float g_acc [NE * 64];
__device__ __align__(16) float g_acc2[NE * 64];
__device__ float g_csum[NE];
__device__ __align__(16) float g_node[NN * 64];

// ---------------- helpers ----------------
__device__ __forceinline__ u32 bf16hi(float v) {      // RNE bf16, bits in top half
    u32 u = __float_as_uint(v);
    return (u + 0x7FFFu + ((u >> 16) & 1u)) & 0xFFFF0000u;
}
// pack (v0 -> low 16, v1 -> high 16) hi and lo parts
__device__ __forceinline__ void pack2(float v0, float v1, u32& h, u32& l) {
    u32 h0 = bf16hi(v0), h1 = bf16hi(v1);
    h = (h0 >> 16) | h1;
    u32 l0 = bf16hi(v0 - __uint_as_float(h0));
    u32 l1 = bf16hi(v1 - __uint_as_float(h1));
    l = (l0 >> 16) | l1;
}
__device__ __forceinline__ void MMA(float* c, const u32* a, const u32* b) {
    asm volatile("mma.sync.aligned.m16n8k16.row.col.f32.bf16.bf16.f32 "
        "{%0,%1,%2,%3}, {%4,%5,%6,%7}, {%8,%9}, {%0,%1,%2,%3};"
        : "+f"(c[0]), "+f"(c[1]), "+f"(c[2]), "+f"(c[3])
        : "r"(a[0]), "r"(a[1]), "r"(a[2]), "r"(a[3]), "r"(b[0]), "r"(b[1]));
}
__device__ __forceinline__ void red2(float* p, float a, float b) {
    asm volatile("red.global.add.v2.f32 [%0], {%1,%2};" :: "l"(p), "f"(a), "f"(b) : "memory");
}

// ---------------- zero scratch: 500x256 = NE*64 ----------------
__global__ void zero_scratch_kernel() {
    int i = blockIdx.x * 256 + threadIdx.x;
    g_acc[i]  = 0.f;
    g_acc2[i] = 0.f;
    if (i < NE) g_csum[i] = 0.f;
}

// ---------------- gemm_x: x = fe @ W2, writes xT [npair][d] hi/lo ----------------
__global__ __launch_bounds__(256) void gemm_x_kernel(const float* __restrict__ Fe,
                                                     const float* __restrict__ W2) {
    __shared__ __align__(16) float Fs[64][64];
    __shared__ __align__(16) float Ws[64][64];
    const int t  = threadIdx.x;
    const int n0 = blockIdx.x * 64;
    const int tx = t & 15, ty = t >> 4;
#pragma unroll
    for (int i = 0; i < 16; i++) {
        int idx = t + 256 * i;
        int r = idx >> 6, c = idx & 63;
        int n = n0 + r;
        Fs[r][c] = (n < NN) ? Fe[n * 64 + c] : 0.f;
        Ws[r][c] = W2[idx];
    }
    __syncthreads();
    float a[4][4];
#pragma unroll
    for (int i = 0; i < 4; i++)
#pragma unroll
        for (int j = 0; j < 4; j++) a[i][j] = 0.f;
#pragma unroll
    for (int k = 0; k < 64; k++) {
        float fv[4];
#pragma unroll
        for (int i = 0; i < 4; i++) fv[i] = Fs[ty * 4 + i][k];
        float4 w4 = *(const float4*)&Ws[k][tx * 4];
        float wv[4] = {w4.x, w4.y, w4.z, w4.w};
#pragma unroll
        for (int i = 0; i < 4; i++)
#pragma unroll
            for (int j = 0; j < 4; j++) a[i][j] = fmaf(fv[i], wv[j], a[i][j]);
    }
#pragma unroll
    for (int ip = 0; ip < 2; ip++)
#pragma unroll
        for (int j = 0; j < 4; j++) {
            u32 h, l; pack2(a[2 * ip][j], a[2 * ip + 1][j], h, l);
            int idx = ((n0 >> 1) + ty * 2 + ip) * 64 + tx * 4 + j;
            g_xTh[idx] = h;
            g_xTl[idx] = l;
        }
}

// ---------------- GEMM1/3: acc[e,d] += sum_n exp(adj[n,e]) * B[n,d] ----------------
// MODE 1: exp from adj, caches g_P, B=xT, ones->csum.  MODE 3: loads g_P, B=nT.
template <int MODE>
__global__ __launch_bounds__(256, 2) void gemm_et(const float* __restrict__ A) {
    extern __shared__ __align__(16) char sm[];
    u32* Ah = (u32*)sm;                  // [32 kpair][136]  (m = e, stride%32==8)
    u32* Al = Ah + 32 * 136;
    u32* Bh = Al + 32 * 136;             // [32 kpair][72]   (n = d + ones col 64)
    u32* Bl = Bh + 32 * 72;
    const int t = threadIdx.x, w = t >> 5, lane = t & 31;
    const int g = lane >> 2, tg = lane & 3;
    const int e0 = blockIdx.x * 128;
    const int sp = blockIdx.y;
    const int c0  = sp * 17 + (sp < 7 ? sp : 7);
    const int nch = 17 + (sp < 7 ? 1 : 0);
    const int wm = w >> 1, wn = w & 1;
    const int rowb = wm * 32;
    const int e_l = t & 127, half = t >> 7;
    const u32* __restrict__ BTh = (MODE == 1) ? g_xTh : g_nTh;
    const u32* __restrict__ BTl = (MODE == 1) ? g_xTl : g_nTl;

    float c[2][4][4];
    float ce[2][4];
#pragma unroll
    for (int mt = 0; mt < 2; mt++) {
#pragma unroll
        for (int nt = 0; nt < 4; nt++)
#pragma unroll
            for (int q = 0; q < 4; q++) c[mt][nt][q] = 0.f;
#pragma unroll
        for (int q = 0; q < 4; q++) ce[mt][q] = 0.f;
    }

    for (int ci = 0; ci < nch; ci++) {
        const int n0  = (c0 + ci) * 64;
        const int np0 = n0 >> 1;
        // ---- fill A tile [32 kpair][128 e] ----
        if (MODE == 1) {
            const bool e_ok = (e0 + e_l) < NE;
#pragma unroll
            for (int i = 0; i < 16; i++) {
                int p_l = 2 * i + half;
                int n = n0 + 2 * p_l;
                float v0 = 0.f, v1 = 0.f;
                if (e_ok) {
                    if (n < NN)     v0 = __expf(A[(size_t)n * NE + e0 + e_l]);
                    if (n + 1 < NN) v1 = __expf(A[(size_t)(n + 1) * NE + e0 + e_l]);
                }
                u32 h, l; pack2(v0, v1, h, l);
                Ah[p_l * 136 + e_l] = h;
                Al[p_l * 136 + e_l] = l;
                size_t gi = (size_t)(np0 + p_l) * EPAD + e0 + e_l;
                g_Ph[gi] = h;
                g_Pl[gi] = l;
            }
        } else {
#pragma unroll
            for (int i = 0; i < 16; i++) {
                int p_l = 2 * i + half;
                size_t gi = (size_t)(np0 + p_l) * EPAD + e0 + e_l;
                Ah[p_l * 136 + e_l] = g_Ph[gi];
                Al[p_l * 136 + e_l] = g_Pl[gi];
            }
        }
        // ---- fill B tile [32 kpair][64 d] + ones col ----
        {
            int d = t & 63;
#pragma unroll
            for (int i = 0; i < 8; i++) {
                int r = (t >> 6) + 4 * i;
                Bh[r * 72 + d] = BTh[(np0 + r) * 64 + d];
                Bl[r * 72 + d] = BTl[(np0 + r) * 64 + d];
            }
            int r = t >> 3, cc = 64 + (t & 7);
            Bh[r * 72 + cc] = (MODE == 1 && cc == 64) ? 0x3F803F80u : 0u;
            Bl[r * 72 + cc] = 0u;
        }
        __syncthreads();
        // ---- mma ----
#pragma unroll
        for (int kt = 0; kt < 4; kt++) {
            int kp = kt * 8;
            u32 ah[2][4], al[2][4];
#pragma unroll
            for (int mt = 0; mt < 2; mt++) {
                int rb = rowb + mt * 16;
                ah[mt][0] = Ah[(kp + tg) * 136 + rb + g];
                ah[mt][1] = Ah[(kp + tg) * 136 + rb + g + 8];
                ah[mt][2] = Ah[(kp + tg + 4) * 136 + rb + g];
                ah[mt][3] = Ah[(kp + tg + 4) * 136 + rb + g + 8];
                al[mt][0] = Al[(kp + tg) * 136 + rb + g];
                al[mt][1] = Al[(kp + tg) * 136 + rb + g + 8];
                al[mt][2] = Al[(kp + tg + 4) * 136 + rb + g];
                al[mt][3] = Al[(kp + tg + 4) * 136 + rb + g + 8];
            }
#pragma unroll
            for (int nt = 0; nt < 4; nt++) {
                int cb = wn * 32 + nt * 8;
                u32 bh[2] = { Bh[(kp + tg) * 72 + cb + g], Bh[(kp + tg + 4) * 72 + cb + g] };
                u32 bl[2] = { Bl[(kp + tg) * 72 + cb + g], Bl[(kp + tg + 4) * 72 + cb + g] };
#pragma unroll
                for (int mt = 0; mt < 2; mt++) {
                    MMA(c[mt][nt], ah[mt], bh);
                    MMA(c[mt][nt], ah[mt], bl);
                    MMA(c[mt][nt], al[mt], bh);
                }
            }
            if (MODE == 1 && wn == 1) {
                u32 be[2] = { Bh[(kp + tg) * 72 + 64 + g], Bh[(kp + tg + 4) * 72 + 64 + g] };
#pragma unroll
                for (int mt = 0; mt < 2; mt++) {
                    MMA(ce[mt], ah[mt], be);
                    MMA(ce[mt], al[mt], be);
                }
            }
        }
        __syncthreads();
    }
    // ---- epilogue: split-K reduce ----
    float* acc = (MODE == 1) ? g_acc : g_acc2;
#pragma unroll
    for (int mt = 0; mt < 2; mt++)
#pragma unroll
        for (int nt = 0; nt < 4; nt++) {
            int row = e0 + rowb + mt * 16 + g;
            int col = wn * 32 + nt * 8 + 2 * tg;
            if (row < NE)     red2(&acc[row * 64 + col],       c[mt][nt][0], c[mt][nt][1]);
            if (row + 8 < NE) red2(&acc[(row + 8) * 64 + col], c[mt][nt][2], c[mt][nt][3]);
        }
    if (MODE == 1 && wn == 1 && tg == 0) {
#pragma unroll
        for (int mt = 0; mt < 2; mt++) {
            int row = e0 + rowb + mt * 16 + g;
            if (row < NE)     atomicAdd(&g_csum[row],     ce[mt][0]);
            if (row + 8 < NE) atomicAdd(&g_csum[row + 8], ce[mt][2]);
        }
    }
}

// ---------------- finalize1: edge = relu(acc/csum); y = edge@W3 -> yT [epair][d] --
__global__ __launch_bounds__(256) void finalize1_kernel(const float* __restrict__ W3) {
    __shared__ __align__(16) float Es[64][64];
    __shared__ __align__(16) float Ws[64][64];
    const int t  = threadIdx.x;
    const int e0 = blockIdx.x * 64;
    const int tx = t & 15, ty = t >> 4;
#pragma unroll
    for (int i = 0; i < 16; i++) {
        int idx = t + 256 * i;
        int r = idx >> 6, cc = idx & 63;
        int ge = e0 + r;
        float v = 0.f;
        if (ge < NE) v = fmaxf(g_acc[ge * 64 + cc] / g_csum[ge], 0.f);
        Es[r][cc] = v;
        Ws[r][cc] = W3[idx];
    }
    __syncthreads();
    float a[4][4];
#pragma unroll
    for (int i = 0; i < 4; i++)
#pragma unroll
        for (int j = 0; j < 4; j++) a[i][j] = 0.f;
#pragma unroll
    for (int k = 0; k < 64; k++) {
        float ev[4];
#pragma unroll
        for (int i = 0; i < 4; i++) ev[i] = Es[ty * 4 + i][k];
        float4 w4 = *(const float4*)&Ws[k][tx * 4];
        float wv[4] = {w4.x, w4.y, w4.z, w4.w};
#pragma unroll
        for (int i = 0; i < 4; i++)
#pragma unroll
            for (int j = 0; j < 4; j++) a[i][j] = fmaf(ev[i], wv[j], a[i][j]);
    }
#pragma unroll
    for (int ip = 0; ip < 2; ip++)
#pragma unroll
        for (int j = 0; j < 4; j++) {
            u32 h, l; pack2(a[2 * ip][j], a[2 * ip + 1][j], h, l);
            int idx = ((e0 >> 1) + ty * 2 + ip) * 64 + tx * 4 + j;
            g_yTh[idx] = h;
            g_yTl[idx] = l;
        }
}

// ---------------- GEMM2: node = relu((exp(adj)@y)/rsum); writes g_node + nT ------
__global__ __launch_bounds__(256, 3) void gemm_n() {
    extern __shared__ __align__(16) char sm[];
    u32* A2h = (u32*)sm;                 // [64 n][36 epair]  (stride%32==4)
    u32* A2l = A2h + 64 * 36;
    u32* Bh  = A2l + 64 * 36;            // [32 epair][72]
    u32* Bl  = Bh + 32 * 72;
    float* rsum   = (float*)(Bl + 32 * 72);  // [64]
    float* bounce = (float*)sm;          // [64][68] overlay on A2 after mma done
    const int t = threadIdx.x, w = t >> 5, lane = t & 31;
    const int g = lane >> 2, tg = lane & 3;
    const int p0 = blockIdx.x * 32;      // n window = 64
    const int wm = w >> 1, wn = w & 1;
    const int rowb = wm * 16;

    float c[4][4];
    float ce[4];
#pragma unroll
    for (int nt = 0; nt < 4; nt++)
#pragma unroll
        for (int q = 0; q < 4; q++) c[nt][q] = 0.f;
#pragma unroll
    for (int q = 0; q < 4; q++) ce[q] = 0.f;

    for (int ech = 0; ech < 32; ech++) {
        const int e0 = ech * 64, ep0 = ech * 32;
        // ---- fill A2 [64 n][32 epair] via prmt repack of g_P ----
#pragma unroll
        for (int i = 0; i < 4; i++) {
            int pl = w + 8 * i;
            size_t base = (size_t)(p0 + pl) * EPAD + e0 + 2 * lane;
            uint2 vh = *(const uint2*)&g_Ph[base];
            uint2 vl = *(const uint2*)&g_Pl[base];
            A2h[(2 * pl) * 36 + lane]     = __byte_perm(vh.x, vh.y, 0x5410);
            A2h[(2 * pl + 1) * 36 + lane] = __byte_perm(vh.x, vh.y, 0x7632);
            A2l[(2 * pl) * 36 + lane]     = __byte_perm(vl.x, vl.y, 0x5410);
            A2l[(2 * pl + 1) * 36 + lane] = __byte_perm(vl.x, vl.y, 0x7632);
        }
        // ---- fill B [32 epair][64 d] + ones col ----
        {
            int d = t & 63;
#pragma unroll
            for (int i = 0; i < 8; i++) {
                int r = (t >> 6) + 4 * i;
                Bh[r * 72 + d] = g_yTh[(ep0 + r) * 64 + d];
                Bl[r * 72 + d] = g_yTl[(ep0 + r) * 64 + d];
            }
            int r = t >> 3, cc = 64 + (t & 7);
            Bh[r * 72 + cc] = (cc == 64) ? 0x3F803F80u : 0u;
            Bl[r * 72 + cc] = 0u;
        }
        __syncthreads();
#pragma unroll
        for (int kt = 0; kt < 4; kt++) {
            int kp = kt * 8;
            u32 ah[4] = { A2h[(rowb + g) * 36 + kp + tg],     A2h[(rowb + g + 8) * 36 + kp + tg],
                          A2h[(rowb + g) * 36 + kp + tg + 4], A2h[(rowb + g + 8) * 36 + kp + tg + 4] };
            u32 al[4] = { A2l[(rowb + g) * 36 + kp + tg],     A2l[(rowb + g + 8) * 36 + kp + tg],
                          A2l[(rowb + g) * 36 + kp + tg + 4], A2l[(rowb + g + 8) * 36 + kp + tg + 4] };
#pragma unroll
            for (int nt = 0; nt < 4; nt++) {
                int cb = wn * 32 + nt * 8;
                u32 bh[2] = { Bh[(kp + tg) * 72 + cb + g], Bh[(kp + tg + 4) * 72 + cb + g] };
                u32 bl[2] = { Bl[(kp + tg) * 72 + cb + g], Bl[(kp + tg + 4) * 72 + cb + g] };
                MMA(c[nt], ah, bh);
                MMA(c[nt], ah, bl);
                MMA(c[nt], al, bh);
            }
            if (wn == 1) {
                u32 be[2] = { Bh[(kp + tg) * 72 + 64 + g], Bh[(kp + tg + 4) * 72 + 64 + g] };
                MMA(ce, ah, be);
                MMA(ce, al, be);
            }
        }
        __syncthreads();
    }
    // ---- rsum from ones column ----
    if (wn == 1 && tg == 0) {
        rsum[rowb + g]     = ce[0];
        rsum[rowb + g + 8] = ce[2];
    }
    __syncthreads();
    float s0 = rsum[rowb + g],     ri0 = (s0 > 0.f) ? 1.f / s0 : 0.f;
    float s1 = rsum[rowb + g + 8], ri1 = (s1 > 0.f) ? 1.f / s1 : 0.f;
    __syncthreads();   // rsum read before bounce overlay... (rsum region separate; sync for A2 reuse)
#pragma unroll
    for (int nt = 0; nt < 4; nt++) {
        int col = wn * 32 + nt * 8 + 2 * tg;
        bounce[(rowb + g) * 68 + col]         = fmaxf(c[nt][0], 0.f) * ri0;
        bounce[(rowb + g) * 68 + col + 1]     = fmaxf(c[nt][1], 0.f) * ri0;
        bounce[(rowb + g + 8) * 68 + col]     = fmaxf(c[nt][2], 0.f) * ri1;
        bounce[(rowb + g + 8) * 68 + col + 1] = fmaxf(c[nt][3], 0.f) * ri1;
    }
    __syncthreads();
    const int n0 = p0 * 2;
#pragma unroll
    for (int i = 0; i < 4; i++) {            // g_node fp32 coalesced
        int idx = t + 256 * i;
        int r = idx >> 4, q = idx & 15;
        if (n0 + r < NN)
            *(float4*)&g_node[(n0 + r) * 64 + q * 4] = *(const float4*)&bounce[r * 68 + q * 4];
    }
#pragma unroll
    for (int i = 0; i < 8; i++) {            // nT [npair][d] hi/lo
        int idx = t + 256 * i;
        int d = idx & 63, pp = idx >> 6;
        u32 h, l;
        pack2(bounce[(2 * pp) * 68 + d], bounce[(2 * pp + 1) * 68 + d], h, l);
        g_nTh[(p0 + pp) * 64 + d] = h;
        g_nTl[(p0 + pp) * 64 + d] = l;
    }
}

// ---------------- finalize3: out_edges = BN(relu(acc2/csum)) ----------------
__global__ void finalize3_kernel(const float* __restrict__ gamma,
                                 const float* __restrict__ beta,
                                 float* __restrict__ out_edges) {
    int idx = blockIdx.x * 256 + threadIdx.x;
    if (idx < NE * 64) {
        int e = idx >> 6, d = idx & 63;
        float v = fmaxf(g_acc2[idx] / g_csum[e], 0.f);
        out_edges[idx] = v * (gamma[d] * rsqrtf(1.f + 1e-5f)) + beta[d];
    }
}

// ---------------- fusion: fe' = s0*fe + (1-s0)*BN(node) ----------------
__global__ __launch_bounds__(256) void fusion_kernel(const float* __restrict__ fe_old,
                                                     const float* __restrict__ gamma,
                                                     const float* __restrict__ beta,
                                                     const float* __restrict__ w1,
                                                     const float* __restrict__ b1,
                                                     const float* __restrict__ w2,
                                                     float* __restrict__ out_nodes) {
    __shared__ float w1s[64 * 64];
    __shared__ float b1s[64], w2s[64], gs[64], bs[64];
    const int t = threadIdx.x;
#pragma unroll
    for (int i = 0; i < 16; i++) w1s[t + 256 * i] = w1[t + 256 * i];
    if (t < 64) {
        b1s[t] = b1[t]; w2s[t] = w2[t];
        gs[t] = gamma[t] * rsqrtf(1.f + 1e-5f); bs[t] = beta[t];
    }
    __syncthreads();
    const int warp = t >> 5, lane = t & 31;
    const int nbase = blockIdx.x * 32 + warp * 4;
    for (int it = 0; it < 4; it++) {
        int n = nbase + it;
        if (n >= NN) break;
        int off = n * 64;
        float f0 = fe_old[off + lane], f1 = fe_old[off + lane + 32];
        float nb0 = fmaf(g_node[off + lane],      gs[lane],      bs[lane]);
        float nb1 = fmaf(g_node[off + lane + 32], gs[lane + 32], bs[lane + 32]);
        float ha0 = b1s[lane], ha1 = b1s[lane + 32];
        float hb0 = ha0, hb1 = ha1;
#pragma unroll
        for (int k = 0; k < 64; k++) {
            float fk = __shfl_sync(0xffffffffu, (k < 32) ? f0 : f1, k & 31);
            float nk = __shfl_sync(0xffffffffu, (k < 32) ? nb0 : nb1, k & 31);
            float wa = w1s[k * 64 + lane], wb = w1s[k * 64 + lane + 32];
            ha0 = fmaf(fk, wa, ha0); ha1 = fmaf(fk, wb, ha1);
            hb0 = fmaf(nk, wa, hb0); hb1 = fmaf(nk, wb, hb1);
        }
        ha0 = tanhf(ha0); ha1 = tanhf(ha1);
        hb0 = tanhf(hb0); hb1 = tanhf(hb1);
        float pa = ha0 * w2s[lane] + ha1 * w2s[lane + 32];
        float pb = hb0 * w2s[lane] + hb1 * w2s[lane + 32];
#pragma unroll
        for (int o = 16; o > 0; o >>= 1) {
            pa += __shfl_down_sync(0xffffffffu, pa, o);
            pb += __shfl_down_sync(0xffffffffu, pb, o);
        }
        pa = __shfl_sync(0xffffffffu, pa, 0);
        pb = __shfl_sync(0xffffffffu, pb, 0);
        float s0 = 1.f / (1.f + expf(pb - pa));
        out_nodes[off + lane]      = s0 * f0 + (1.f - s0) * nb0;
        out_nodes[off + lane + 32] = s0 * f1 + (1.f - s0) * nb1;
    }
}

// ---------------- launch ----------------
#define SM_ET ((32*136*2 + 32*72*2) * 4)            // 53248
#define SM_N  ((64*36*2 + 32*72*2) * 4 + 256)       // 37120

extern "C" void kernel_launch(void* const* d_in, const int* in_sizes, int n_in,
                              void* d_out, int out_size) {
    const float* fe    = (const float*)d_in[0];
    const float* adj   = (const float*)d_in[1];
    const float* W2    = (const float*)d_in[2];
    const float* W3    = (const float*)d_in[3];
    const float* gamma = (const float*)d_in[4];
    const float* beta  = (const float*)d_in[5];
    const float* fw1   = (const float*)d_in[6];
    const float* fb1   = (const float*)d_in[7];
    const float* fw2   = (const float*)d_in[8];
    float* out = (float*)d_out;

    cudaFuncSetAttribute((const void*)gemm_et<1>, cudaFuncAttributeMaxDynamicSharedMemorySize, SM_ET);
    cudaFuncSetAttribute((const void*)gemm_et<3>, cudaFuncAttributeMaxDynamicSharedMemorySize, SM_ET);
    cudaFuncSetAttribute((const void*)gemm_n,     cudaFuncAttributeMaxDynamicSharedMemorySize, SM_N);

    const float* fe_cur = fe;
    for (int s = 0; s < NS; s++) {
        const float* A   = adj + (size_t)s * NN * NE;
        float* out_nodes = out + (size_t)s * (NN + NE) * 64;
        float* out_edges = out_nodes + (size_t)NN * 64;

        zero_scratch_kernel<<<500, 256>>>();
        gemm_x_kernel<<<313, 256>>>(fe_cur, W2);
        gemm_et<1><<<dim3(16, 18), 256, SM_ET>>>(A);   // exp + cache g_P + edge_pre + csum
        finalize1_kernel<<<32, 256>>>(W3);             // y = relu(edge)@W3 -> yT
        gemm_n<<<313, 256, SM_N>>>();                  // node + nT (+rsum via ones col)
        gemm_et<3><<<dim3(16, 18), 256, SM_ET>>>(A);   // edge2_pre from cached g_P
        finalize3_kernel<<<500, 256>>>(gamma, beta, out_edges);
        fusion_kernel<<<625, 256>>>(fe_cur, gamma, beta, fw1, fb1, fw2, out_nodes);

        fe_cur = out_nodes;
    }
}